// round 1
// baseline (speedup 1.0000x reference)
#include <cuda_runtime.h>

// ---------------- scratch (no cudaMalloc allowed) ----------------
// B*N*L*H_DIM = 4*64*256*512 = 33,554,432 floats each (128 MiB)
#define ELEMS 33554432
__device__ float g_q[ELEMS];
__device__ float g_k[ELEMS];
__device__ float g_v[ELEMS];
__device__ float g_ao[ELEMS];

#define BM 64
#define BN 64
#define KC 32

// C[M,N] = A[M,K] @ W[K,N] + bias ; A,W row-major
__device__ __forceinline__ void sgemm_body(
    const float* __restrict__ A, const float* __restrict__ W,
    const float* __restrict__ bias, float* __restrict__ C,
    int N, int K)
{
    __shared__ float As[KC][BM];
    __shared__ float Bs[KC][BN];
    int tid = threadIdx.x;
    int tx = tid & 15, ty = tid >> 4;
    int m0 = blockIdx.y * BM;
    int n0 = blockIdx.x * BN;

    float acc[4][4] = {};

    for (int kc = 0; kc < K; kc += KC) {
        // A tile (BM x KC) -> As[k][m] (transposed)
        #pragma unroll
        for (int i = 0; i < 2; i++) {
            int f = tid * 2 + i;         // 0..511
            int m = f >> 3;              // 8 float4 per row (KC=32)
            int kf = f & 7;
            float4 a = *(const float4*)&A[(size_t)(m0 + m) * K + kc + kf * 4];
            As[kf * 4 + 0][m] = a.x;
            As[kf * 4 + 1][m] = a.y;
            As[kf * 4 + 2][m] = a.z;
            As[kf * 4 + 3][m] = a.w;
        }
        // W tile (KC x BN) -> Bs[k][n]
        #pragma unroll
        for (int i = 0; i < 2; i++) {
            int f = tid * 2 + i;
            int k = f >> 4;              // 16 float4 per row (BN=64)
            int nf = f & 15;
            *(float4*)&Bs[k][nf * 4] =
                *(const float4*)&W[(size_t)(kc + k) * N + n0 + nf * 4];
        }
        __syncthreads();

        #pragma unroll
        for (int k = 0; k < KC; k++) {
            float4 a4 = *(const float4*)&As[k][ty * 4];
            float4 b4 = *(const float4*)&Bs[k][tx * 4];
            float a[4] = {a4.x, a4.y, a4.z, a4.w};
            float b[4] = {b4.x, b4.y, b4.z, b4.w};
            #pragma unroll
            for (int i = 0; i < 4; i++)
                #pragma unroll
                for (int j = 0; j < 4; j++)
                    acc[i][j] += a[i] * b[j];
        }
        __syncthreads();
    }

    float4 bb = *(const float4*)&bias[n0 + tx * 4];
    #pragma unroll
    for (int i = 0; i < 4; i++) {
        float4 o;
        o.x = acc[i][0] + bb.x;
        o.y = acc[i][1] + bb.y;
        o.z = acc[i][2] + bb.z;
        o.w = acc[i][3] + bb.w;
        *(float4*)&C[(size_t)(m0 + ty * 4 + i) * N + n0 + tx * 4] = o;
    }
}

// blockIdx.z selects q/k/v projection
__global__ __launch_bounds__(256) void qkv_proj_kernel(
    const float* __restrict__ qin, const float* __restrict__ kin,
    const float* __restrict__ vin,
    const float* __restrict__ Wq, const float* __restrict__ bq,
    const float* __restrict__ Wk, const float* __restrict__ bk,
    const float* __restrict__ Wv, const float* __restrict__ bv)
{
    const float* A; const float* W; const float* bias; float* C;
    if (blockIdx.z == 0)      { A = qin; W = Wq; bias = bq; C = g_q; }
    else if (blockIdx.z == 1) { A = kin; W = Wk; bias = bk; C = g_k; }
    else                      { A = vin; W = Wv; bias = bv; C = g_v; }
    sgemm_body(A, W, bias, C, 512, 128);
}

__global__ __launch_bounds__(256) void out_proj_kernel(
    const float* __restrict__ Wo, const float* __restrict__ bo,
    float* __restrict__ out)
{
    sgemm_body(g_ao, Wo, bo, out, 512, 512);
}

// One block per (head, b*n). Each thread owns one q-row (L=256 threads).
// K,V tiles live in dynamic smem (2 * 256*64 floats = 128 KB).
__global__ __launch_bounds__(256, 1) void attn_kernel()
{
    extern __shared__ float sm[];
    float* ks = sm;                  // [256][64]
    float* vs = sm + 256 * 64;       // [256][64]

    int h  = blockIdx.x;             // 0..7
    int bn = blockIdx.y;             // 0..255
    int t  = threadIdx.x;            // q row

    size_t base = (size_t)bn * 256 * 512 + (size_t)h * 64;

    // cooperative load of K,V tiles
    #pragma unroll
    for (int i = 0; i < 16; i++) {
        int f   = t + i * 256;       // 0..4095
        int row = f >> 4;
        int c4  = f & 15;
        *(float4*)&ks[row * 64 + c4 * 4] =
            *(const float4*)&g_k[base + (size_t)row * 512 + c4 * 4];
        *(float4*)&vs[row * 64 + c4 * 4] =
            *(const float4*)&g_v[base + (size_t)row * 512 + c4 * 4];
    }

    // q row into registers, pre-scaled by 1/sqrt(64)
    float q[64];
    #pragma unroll
    for (int i = 0; i < 16; i++) {
        float4 a = *(const float4*)&g_q[base + (size_t)t * 512 + i * 4];
        q[i * 4 + 0] = a.x * 0.125f;
        q[i * 4 + 1] = a.y * 0.125f;
        q[i * 4 + 2] = a.z * 0.125f;
        q[i * 4 + 3] = a.w * 0.125f;
    }
    __syncthreads();

    float out[64] = {};
    float denom = 0.0f;

    for (int j = 0; j < 256; j++) {
        const float* kr = &ks[j * 64];
        // 8 partial accumulators to break the RAW chain
        float s0 = 0.f, s1 = 0.f, s2 = 0.f, s3 = 0.f;
        float s4 = 0.f, s5 = 0.f, s6 = 0.f, s7 = 0.f;
        #pragma unroll
        for (int d = 0; d < 64; d += 8) {
            s0 += q[d + 0] * kr[d + 0];
            s1 += q[d + 1] * kr[d + 1];
            s2 += q[d + 2] * kr[d + 2];
            s3 += q[d + 3] * kr[d + 3];
            s4 += q[d + 4] * kr[d + 4];
            s5 += q[d + 5] * kr[d + 5];
            s6 += q[d + 6] * kr[d + 6];
            s7 += q[d + 7] * kr[d + 7];
        }
        float s = ((s0 + s1) + (s2 + s3)) + ((s4 + s5) + (s6 + s7));
        float e = __expf(s);
        denom += e;
        const float* vr = &vs[j * 64];
        #pragma unroll
        for (int d = 0; d < 64; d++)
            out[d] += e * vr[d];
    }

    float inv = 1.0f / denom;
    #pragma unroll
    for (int i = 0; i < 16; i++) {
        float4 o;
        o.x = out[i * 4 + 0] * inv;
        o.y = out[i * 4 + 1] * inv;
        o.z = out[i * 4 + 2] * inv;
        o.w = out[i * 4 + 3] * inv;
        *(float4*)&g_ao[base + (size_t)t * 512 + i * 4] = o;
    }
}

extern "C" void kernel_launch(void* const* d_in, const int* in_sizes, int n_in,
                              void* d_out, int out_size)
{
    const float* query = (const float*)d_in[0];
    const float* key   = (const float*)d_in[1];
    const float* value = (const float*)d_in[2];
    const float* Wq    = (const float*)d_in[3];
    const float* bq    = (const float*)d_in[4];
    const float* Wk    = (const float*)d_in[5];
    const float* bk    = (const float*)d_in[6];
    const float* Wv    = (const float*)d_in[7];
    const float* bv    = (const float*)d_in[8];
    const float* Wo    = (const float*)d_in[9];
    const float* bo    = (const float*)d_in[10];
    float* out = (float*)d_out;

    // M = B*N*L = 65536
    dim3 gproj(512 / BN, 65536 / BM, 3);
    qkv_proj_kernel<<<gproj, 256>>>(query, key, value, Wq, bq, Wk, bk, Wv, bv);

    static_assert(2 * 256 * 64 * sizeof(float) == 131072, "smem size");
    cudaFuncSetAttribute(attn_kernel,
                         cudaFuncAttributeMaxDynamicSharedMemorySize, 131072);
    dim3 gattn(8, 256);
    attn_kernel<<<gattn, 256, 131072>>>();

    dim3 gout(512 / BN, 65536 / BM);
    out_proj_kernel<<<gout, 256>>>(Wo, bo, out);
}

// round 3
// speedup vs baseline: 3.4323x; 3.4323x over previous
#include <cuda_runtime.h>
#include <cstdint>

// ---------------- scratch (no cudaMalloc allowed) ----------------
// B*N*L*H_DIM = 4*64*256*512 = 33,554,432 floats each (128 MiB)
#define ELEMS 33554432
__device__ float g_q[ELEMS];
__device__ float g_k[ELEMS];
__device__ float g_v[ELEMS];
__device__ float g_ao[ELEMS];

// ---------------- tf32 helpers ----------------
__device__ __forceinline__ uint32_t f2tf(float x) {
    uint32_t r;
    asm("cvt.rna.tf32.f32 %0, %1;" : "=r"(r) : "f"(x));
    return r;
}

// D += A(16x8) * B(8x8), tf32 inputs, f32 accum
__device__ __forceinline__ void mma8(float* d, const uint32_t* a, const uint32_t* b) {
    asm volatile(
        "mma.sync.aligned.m16n8k8.row.col.f32.tf32.tf32.f32 "
        "{%0,%1,%2,%3}, {%4,%5,%6,%7}, {%8,%9}, {%0,%1,%2,%3};"
        : "+f"(d[0]), "+f"(d[1]), "+f"(d[2]), "+f"(d[3])
        : "r"(a[0]), "r"(a[1]), "r"(a[2]), "r"(a[3]), "r"(b[0]), "r"(b[1]));
}

// ================= projection GEMM: C[M,N] = A[M,K] @ W[K,N] + bias =========
// block tile 128x128, BK=16, 8 warps (4 along M x 2 along N), warp tile 32x64
#define AS_STRIDE 20   // 16 + 4 pad -> conflict-free A-frag LDS
#define BS_STRIDE 136  // 128 + 8 pad -> conflict-free B-frag LDS

__device__ __forceinline__ void gemm_body(
    const float* __restrict__ A, const float* __restrict__ W,
    const float* __restrict__ bias, float* __restrict__ C,
    int N, int K)
{
    __shared__ uint32_t As[128 * AS_STRIDE];
    __shared__ uint32_t Bs[16 * BS_STRIDE];

    int tid  = threadIdx.x;
    int lane = tid & 31, warp = tid >> 5;
    int g = lane >> 2, t = lane & 3;
    int wm = (warp & 3) * 32;    // warp row base in block tile
    int wn = (warp >> 2) * 64;   // warp col base
    int m0 = blockIdx.y * 128;
    int n0 = blockIdx.x * 128;

    float acc[2][8][4] = {};

    for (int kc = 0; kc < K; kc += 16) {
        // A tile 128x16 -> As (tf32)
        #pragma unroll
        for (int i = 0; i < 2; i++) {
            int f = tid + i * 256;          // 0..511 float4 slots
            int r = f >> 2, c4 = (f & 3) * 4;
            float4 v = *(const float4*)&A[(size_t)(m0 + r) * K + kc + c4];
            As[r * AS_STRIDE + c4 + 0] = f2tf(v.x);
            As[r * AS_STRIDE + c4 + 1] = f2tf(v.y);
            As[r * AS_STRIDE + c4 + 2] = f2tf(v.z);
            As[r * AS_STRIDE + c4 + 3] = f2tf(v.w);
        }
        // W tile 16x128 -> Bs (tf32)
        #pragma unroll
        for (int i = 0; i < 2; i++) {
            int f = tid + i * 256;
            int r = f >> 5, c4 = (f & 31) * 4;
            float4 v = *(const float4*)&W[(size_t)(kc + r) * N + n0 + c4];
            Bs[r * BS_STRIDE + c4 + 0] = f2tf(v.x);
            Bs[r * BS_STRIDE + c4 + 1] = f2tf(v.y);
            Bs[r * BS_STRIDE + c4 + 2] = f2tf(v.z);
            Bs[r * BS_STRIDE + c4 + 3] = f2tf(v.w);
        }
        __syncthreads();

        #pragma unroll
        for (int ks = 0; ks < 2; ks++) {
            int k0 = ks * 8;
            uint32_t a[2][4], b[8][2];
            #pragma unroll
            for (int mt = 0; mt < 2; mt++) {
                int r = wm + 16 * mt + g;
                a[mt][0] = As[r * AS_STRIDE + k0 + t];
                a[mt][1] = As[(r + 8) * AS_STRIDE + k0 + t];
                a[mt][2] = As[r * AS_STRIDE + k0 + 4 + t];
                a[mt][3] = As[(r + 8) * AS_STRIDE + k0 + 4 + t];
            }
            #pragma unroll
            for (int nt = 0; nt < 8; nt++) {
                int cb = wn + 8 * nt + g;
                b[nt][0] = Bs[(k0 + t) * BS_STRIDE + cb];
                b[nt][1] = Bs[(k0 + 4 + t) * BS_STRIDE + cb];
            }
            #pragma unroll
            for (int mt = 0; mt < 2; mt++)
                #pragma unroll
                for (int nt = 0; nt < 8; nt++)
                    mma8(acc[mt][nt], a[mt], b[nt]);
        }
        __syncthreads();
    }

    // epilogue: + bias, store float2 pairs
    #pragma unroll
    for (int mt = 0; mt < 2; mt++) {
        int r0 = m0 + wm + 16 * mt + g;
        #pragma unroll
        for (int nt = 0; nt < 8; nt++) {
            int col = n0 + wn + 8 * nt + 2 * t;
            float b0 = bias[col], b1 = bias[col + 1];
            float2 v0 = {acc[mt][nt][0] + b0, acc[mt][nt][1] + b1};
            float2 v1 = {acc[mt][nt][2] + b0, acc[mt][nt][3] + b1};
            *(float2*)&C[(size_t)r0 * N + col] = v0;
            *(float2*)&C[(size_t)(r0 + 8) * N + col] = v1;
        }
    }
}

__global__ __launch_bounds__(256) void qkv_proj_kernel(
    const float* __restrict__ qin, const float* __restrict__ kin,
    const float* __restrict__ vin,
    const float* __restrict__ Wq, const float* __restrict__ bq,
    const float* __restrict__ Wk, const float* __restrict__ bk,
    const float* __restrict__ Wv, const float* __restrict__ bv)
{
    const float* A; const float* W; const float* bias; float* C;
    if (blockIdx.z == 0)      { A = qin; W = Wq; bias = bq; C = g_q; }
    else if (blockIdx.z == 1) { A = kin; W = Wk; bias = bk; C = g_k; }
    else                      { A = vin; W = Wv; bias = bv; C = g_v; }
    gemm_body(A, W, bias, C, 512, 128);
}

__global__ __launch_bounds__(256) void out_proj_kernel(
    const float* __restrict__ Wo, const float* __restrict__ bo,
    float* __restrict__ out)
{
    gemm_body(g_ao, Wo, bo, out, 512, 512);
}

// ================= attention: one block per (bn, h) =========================
// 256 threads = 8 warps, each warp owns 32 q-rows.
// K,V (256x64) in smem as tf32 (stride 72, conflict-free B-frag loads).
// Loop over 4 key-chunks of 64: S = Q K^T (mma) -> exp -> P (per-warp smem
// buffer, stride 68) -> O += P V (mma). Softmax denominator via shfl.
#define KV_STRIDE 72
#define P_STRIDE  68
#define ATTN_SMEM ((2 * 256 * KV_STRIDE + 8 * 32 * P_STRIDE) * 4)  // 217088 B

__global__ __launch_bounds__(256, 1) void attn_kernel()
{
    extern __shared__ uint32_t sm[];
    uint32_t* Ks = sm;
    uint32_t* Vs = sm + 256 * KV_STRIDE;
    int tid = threadIdx.x, lane = tid & 31, warp = tid >> 5;
    int g = lane >> 2, t = lane & 3;
    uint32_t* Pb = sm + 2 * 256 * KV_STRIDE + warp * (32 * P_STRIDE);

    int h  = blockIdx.x;     // 0..7
    int bn = blockIdx.y;     // 0..255
    size_t base = (size_t)bn * 131072 + (size_t)h * 64;  // 256*512

    // cooperative K,V load -> tf32 smem
    #pragma unroll
    for (int i = 0; i < 16; i++) {
        int f = tid + i * 256;          // 4096 float4 slots
        int r = f >> 4, c4 = (f & 15) * 4;
        float4 kv = *(const float4*)&g_k[base + (size_t)r * 512 + c4];
        Ks[r * KV_STRIDE + c4 + 0] = f2tf(kv.x);
        Ks[r * KV_STRIDE + c4 + 1] = f2tf(kv.y);
        Ks[r * KV_STRIDE + c4 + 2] = f2tf(kv.z);
        Ks[r * KV_STRIDE + c4 + 3] = f2tf(kv.w);
        float4 vv = *(const float4*)&g_v[base + (size_t)r * 512 + c4];
        Vs[r * KV_STRIDE + c4 + 0] = f2tf(vv.x);
        Vs[r * KV_STRIDE + c4 + 1] = f2tf(vv.y);
        Vs[r * KV_STRIDE + c4 + 2] = f2tf(vv.z);
        Vs[r * KV_STRIDE + c4 + 3] = f2tf(vv.w);
    }

    // per-warp Q tile (32x64), pre-scaled by 1/sqrt(64), staged via Pb
    int qr0 = warp * 32;
    #pragma unroll
    for (int i = 0; i < 16; i++) {
        int f = lane + i * 32;          // 512 float4 slots
        int r = f >> 4, c4 = (f & 15) * 4;
        float4 qv = *(const float4*)&g_q[base + (size_t)(qr0 + r) * 512 + c4];
        Pb[r * P_STRIDE + c4 + 0] = f2tf(qv.x * 0.125f);
        Pb[r * P_STRIDE + c4 + 1] = f2tf(qv.y * 0.125f);
        Pb[r * P_STRIDE + c4 + 2] = f2tf(qv.z * 0.125f);
        Pb[r * P_STRIDE + c4 + 3] = f2tf(qv.w * 0.125f);
    }
    __syncwarp();

    // Q fragments for all 8 k-steps into registers
    uint32_t q[2][8][4];
    #pragma unroll
    for (int mt = 0; mt < 2; mt++)
        #pragma unroll
        for (int ks = 0; ks < 8; ks++) {
            int r = 16 * mt + g, k0 = 8 * ks;
            q[mt][ks][0] = Pb[r * P_STRIDE + k0 + t];
            q[mt][ks][1] = Pb[(r + 8) * P_STRIDE + k0 + t];
            q[mt][ks][2] = Pb[r * P_STRIDE + k0 + 4 + t];
            q[mt][ks][3] = Pb[(r + 8) * P_STRIDE + k0 + 4 + t];
        }
    __syncthreads();   // K,V visible to all warps

    float o[2][8][4] = {};
    float den[2][2] = {};

    #pragma unroll 1
    for (int c = 0; c < 4; c++) {
        int kb = c * 64;
        // ---- S = Q K^T for this 64-key chunk ----
        float s[2][8][4] = {};
        #pragma unroll
        for (int ks = 0; ks < 8; ks++) {
            int k0 = 8 * ks;
            uint32_t b[8][2];
            #pragma unroll
            for (int nt = 0; nt < 8; nt++) {
                int kr = kb + 8 * nt + g;
                b[nt][0] = Ks[kr * KV_STRIDE + k0 + t];
                b[nt][1] = Ks[kr * KV_STRIDE + k0 + 4 + t];
            }
            #pragma unroll
            for (int mt = 0; mt < 2; mt++)
                #pragma unroll
                for (int nt = 0; nt < 8; nt++)
                    mma8(s[mt][nt], q[mt][ks], b[nt]);
        }
        // ---- exp, denom accumulation, P -> Pb (tf32) ----
        #pragma unroll
        for (int mt = 0; mt < 2; mt++) {
            int r = 16 * mt + g;
            #pragma unroll
            for (int nt = 0; nt < 8; nt++) {
                float e0 = __expf(s[mt][nt][0]);
                float e1 = __expf(s[mt][nt][1]);
                float e2 = __expf(s[mt][nt][2]);
                float e3 = __expf(s[mt][nt][3]);
                den[mt][0] += e0 + e1;
                den[mt][1] += e2 + e3;
                int cc = 8 * nt + 2 * t;
                uint2 p0 = {f2tf(e0), f2tf(e1)};
                uint2 p1 = {f2tf(e2), f2tf(e3)};
                *(uint2*)&Pb[r * P_STRIDE + cc] = p0;
                *(uint2*)&Pb[(r + 8) * P_STRIDE + cc] = p1;
            }
        }
        __syncwarp();
        // ---- O += P V_chunk ----
        #pragma unroll
        for (int ks = 0; ks < 8; ks++) {
            int k0 = 8 * ks;
            uint32_t pa[2][4], b[8][2];
            #pragma unroll
            for (int mt = 0; mt < 2; mt++) {
                int r = 16 * mt + g;
                pa[mt][0] = Pb[r * P_STRIDE + k0 + t];
                pa[mt][1] = Pb[(r + 8) * P_STRIDE + k0 + t];
                pa[mt][2] = Pb[r * P_STRIDE + k0 + 4 + t];
                pa[mt][3] = Pb[(r + 8) * P_STRIDE + k0 + 4 + t];
            }
            #pragma unroll
            for (int nt = 0; nt < 8; nt++) {
                b[nt][0] = Vs[(kb + k0 + t) * KV_STRIDE + 8 * nt + g];
                b[nt][1] = Vs[(kb + k0 + 4 + t) * KV_STRIDE + 8 * nt + g];
            }
            #pragma unroll
            for (int mt = 0; mt < 2; mt++)
                #pragma unroll
                for (int nt = 0; nt < 8; nt++)
                    mma8(o[mt][nt], pa[mt], b[nt]);
        }
        __syncwarp();   // done reading Pb before next chunk overwrites it
    }

    // ---- normalize, store ----
    #pragma unroll
    for (int mt = 0; mt < 2; mt++) {
        float d0 = den[mt][0], d1 = den[mt][1];
        d0 += __shfl_xor_sync(0xffffffffu, d0, 1);
        d0 += __shfl_xor_sync(0xffffffffu, d0, 2);
        d1 += __shfl_xor_sync(0xffffffffu, d1, 1);
        d1 += __shfl_xor_sync(0xffffffffu, d1, 2);
        float inv0 = 1.0f / d0, inv1 = 1.0f / d1;
        int r0 = qr0 + 16 * mt + g;
        #pragma unroll
        for (int nt = 0; nt < 8; nt++) {
            int col = 8 * nt + 2 * t;
            float2 v0 = {o[mt][nt][0] * inv0, o[mt][nt][1] * inv0};
            float2 v1 = {o[mt][nt][2] * inv1, o[mt][nt][3] * inv1};
            *(float2*)&g_ao[base + (size_t)r0 * 512 + col] = v0;
            *(float2*)&g_ao[base + (size_t)(r0 + 8) * 512 + col] = v1;
        }
    }
}

extern "C" void kernel_launch(void* const* d_in, const int* in_sizes, int n_in,
                              void* d_out, int out_size)
{
    const float* query = (const float*)d_in[0];
    const float* key   = (const float*)d_in[1];
    const float* value = (const float*)d_in[2];
    const float* Wq    = (const float*)d_in[3];
    const float* bq    = (const float*)d_in[4];
    const float* Wk    = (const float*)d_in[5];
    const float* bk    = (const float*)d_in[6];
    const float* Wv    = (const float*)d_in[7];
    const float* bv    = (const float*)d_in[8];
    const float* Wo    = (const float*)d_in[9];
    const float* bo    = (const float*)d_in[10];
    float* out = (float*)d_out;

    // M = B*N*L = 65536
    dim3 gproj(512 / 128, 65536 / 128, 3);
    qkv_proj_kernel<<<gproj, 256>>>(query, key, value, Wq, bq, Wk, bk, Wv, bv);

    cudaFuncSetAttribute(attn_kernel,
                         cudaFuncAttributeMaxDynamicSharedMemorySize, ATTN_SMEM);
    dim3 gattn(8, 256);
    attn_kernel<<<gattn, 256, ATTN_SMEM>>>();

    dim3 gout(512 / 128, 65536 / 128);
    out_proj_kernel<<<gout, 256>>>(Wo, bo, out);
}

// round 5
// speedup vs baseline: 3.7016x; 1.0784x over previous
#include <cuda_runtime.h>
#include <cstdint>

// ---------------- scratch (no cudaMalloc allowed) ----------------
#define ELEMS 33554432
__device__ float g_q[ELEMS];
__device__ float g_k[ELEMS];
__device__ float g_v[ELEMS];
__device__ float g_ao[ELEMS];

// ---------------- helpers ----------------
__device__ __forceinline__ uint32_t f2tf(float x) {
    uint32_t r;
    asm("cvt.rna.tf32.f32 %0, %1;" : "=r"(r) : "f"(x));
    return r;
}

__device__ __forceinline__ void mma8(float* d, const uint32_t* a, const uint32_t* b) {
    asm volatile(
        "mma.sync.aligned.m16n8k8.row.col.f32.tf32.tf32.f32 "
        "{%0,%1,%2,%3}, {%4,%5,%6,%7}, {%8,%9}, {%0,%1,%2,%3};"
        : "+f"(d[0]), "+f"(d[1]), "+f"(d[2]), "+f"(d[3])
        : "r"(a[0]), "r"(a[1]), "r"(a[2]), "r"(a[3]), "r"(b[0]), "r"(b[1]));
}

__device__ __forceinline__ uint32_t smem_u32(const void* p) {
    return (uint32_t)__cvta_generic_to_shared(p);
}
__device__ __forceinline__ void cp16(uint32_t dst, const void* src) {
    asm volatile("cp.async.cg.shared.global [%0], [%1], 16;" :: "r"(dst), "l"(src));
}
__device__ __forceinline__ void cp_commit() {
    asm volatile("cp.async.commit_group;");
}
template <int N>
__device__ __forceinline__ void cp_wait() {
    asm volatile("cp.async.wait_group %0;" :: "n"(N));
}

// ================= projection GEMM: C[M,N] = A[M,K] @ W[K,N] + bias =========
// block tile 128x128, BK=16, 3-stage cp.async pipeline.
// smem holds raw f32; cvt.rna.tf32 at fragment-load time.
#define AS_STRIDE 20   // 16 + 4 pad
#define BS_STRIDE 136  // 128 + 8 pad
#define STAGE_F (128 * AS_STRIDE + 16 * BS_STRIDE)  // 4736 floats / stage

__device__ __forceinline__ void gemm_body(
    const float* __restrict__ A, const float* __restrict__ W,
    const float* __restrict__ bias, float* __restrict__ C,
    int N, int K)
{
    __shared__ float smem[3 * STAGE_F];

    int tid  = threadIdx.x;
    int lane = tid & 31, warp = tid >> 5;
    int g = lane >> 2, t = lane & 3;
    int wm = (warp & 3) * 32;
    int wn = (warp >> 2) * 64;
    int m0 = blockIdx.y * 128;
    int n0 = blockIdx.x * 128;

    // per-thread cp.async source/dest offsets (2 A chunks + 2 B chunks)
    // A: f in [0,512): r=f>>2, c4=(f&3)*4 ; B: r=f>>5, c4=(f&31)*4
    int fa0 = tid, fa1 = tid + 256;
    int ar0 = fa0 >> 2, ac0 = (fa0 & 3) * 4;
    int ar1 = fa1 >> 2, ac1 = (fa1 & 3) * 4;
    int br0 = fa0 >> 5, bc0 = (fa0 & 31) * 4;
    int br1 = fa1 >> 5, bc1 = (fa1 & 31) * 4;

    int nTiles = K / 16;

    auto issue = [&](int tile) {
        if (tile < nTiles) {
            float* st = &smem[(tile % 3) * STAGE_F];
            int kc = tile * 16;
            cp16(smem_u32(&st[ar0 * AS_STRIDE + ac0]),
                 &A[(size_t)(m0 + ar0) * K + kc + ac0]);
            cp16(smem_u32(&st[ar1 * AS_STRIDE + ac1]),
                 &A[(size_t)(m0 + ar1) * K + kc + ac1]);
            float* stb = st + 128 * AS_STRIDE;
            cp16(smem_u32(&stb[br0 * BS_STRIDE + bc0]),
                 &W[(size_t)(kc + br0) * N + n0 + bc0]);
            cp16(smem_u32(&stb[br1 * BS_STRIDE + bc1]),
                 &W[(size_t)(kc + br1) * N + n0 + bc1]);
        }
        cp_commit();   // always commit (possibly empty group) to keep count fixed
    };

    float acc[2][8][4] = {};

    issue(0);
    issue(1);

    for (int i = 0; i < nTiles; i++) {
        __syncthreads();          // everyone done computing tile i-1
        issue(i + 2);             // into stage (i+2)%3 == (i-1)%3, now safe
        cp_wait<2>();             // tile i landed
        __syncthreads();

        const float* As = &smem[(i % 3) * STAGE_F];
        const float* Bs = As + 128 * AS_STRIDE;

        #pragma unroll
        for (int ks = 0; ks < 2; ks++) {
            int k0 = ks * 8;
            uint32_t a[2][4], b[8][2];
            #pragma unroll
            for (int mt = 0; mt < 2; mt++) {
                int r = wm + 16 * mt + g;
                a[mt][0] = f2tf(As[r * AS_STRIDE + k0 + t]);
                a[mt][1] = f2tf(As[(r + 8) * AS_STRIDE + k0 + t]);
                a[mt][2] = f2tf(As[r * AS_STRIDE + k0 + 4 + t]);
                a[mt][3] = f2tf(As[(r + 8) * AS_STRIDE + k0 + 4 + t]);
            }
            #pragma unroll
            for (int nt = 0; nt < 8; nt++) {
                int cb = wn + 8 * nt + g;
                b[nt][0] = f2tf(Bs[(k0 + t) * BS_STRIDE + cb]);
                b[nt][1] = f2tf(Bs[(k0 + 4 + t) * BS_STRIDE + cb]);
            }
            #pragma unroll
            for (int mt = 0; mt < 2; mt++)
                #pragma unroll
                for (int nt = 0; nt < 8; nt++)
                    mma8(acc[mt][nt], a[mt], b[nt]);
        }
    }

    // epilogue: + bias, store float2 pairs
    #pragma unroll
    for (int mt = 0; mt < 2; mt++) {
        int r0 = m0 + wm + 16 * mt + g;
        #pragma unroll
        for (int nt = 0; nt < 8; nt++) {
            int col = n0 + wn + 8 * nt + 2 * t;
            float b0 = bias[col], b1 = bias[col + 1];
            float2 v0 = {acc[mt][nt][0] + b0, acc[mt][nt][1] + b1};
            float2 v1 = {acc[mt][nt][2] + b0, acc[mt][nt][3] + b1};
            *(float2*)&C[(size_t)r0 * N + col] = v0;
            *(float2*)&C[(size_t)(r0 + 8) * N + col] = v1;
        }
    }
}

__global__ __launch_bounds__(256, 2) void qkv_proj_kernel(
    const float* __restrict__ qin, const float* __restrict__ kin,
    const float* __restrict__ vin,
    const float* __restrict__ Wq, const float* __restrict__ bq,
    const float* __restrict__ Wk, const float* __restrict__ bk,
    const float* __restrict__ Wv, const float* __restrict__ bv)
{
    const float* A; const float* W; const float* bias; float* C;
    if (blockIdx.z == 0)      { A = qin; W = Wq; bias = bq; C = g_q; }
    else if (blockIdx.z == 1) { A = kin; W = Wk; bias = bk; C = g_k; }
    else                      { A = vin; W = Wv; bias = bv; C = g_v; }
    gemm_body(A, W, bias, C, 512, 128);
}

__global__ __launch_bounds__(256, 2) void out_proj_kernel(
    const float* __restrict__ Wo, const float* __restrict__ bo,
    float* __restrict__ out)
{
    gemm_body(g_ao, Wo, bo, out, 512, 512);
}

// ================= attention (unchanged from round 3) =======================
#define KV_STRIDE 72
#define P_STRIDE  68
#define ATTN_SMEM ((2 * 256 * KV_STRIDE + 8 * 32 * P_STRIDE) * 4)  // 217088 B

__global__ __launch_bounds__(256, 1) void attn_kernel()
{
    extern __shared__ uint32_t sm[];
    uint32_t* Ks = sm;
    uint32_t* Vs = sm + 256 * KV_STRIDE;
    int tid = threadIdx.x, lane = tid & 31, warp = tid >> 5;
    int g = lane >> 2, t = lane & 3;
    uint32_t* Pb = sm + 2 * 256 * KV_STRIDE + warp * (32 * P_STRIDE);

    int h  = blockIdx.x;
    int bn = blockIdx.y;
    size_t base = (size_t)bn * 131072 + (size_t)h * 64;

    #pragma unroll
    for (int i = 0; i < 16; i++) {
        int f = tid + i * 256;
        int r = f >> 4, c4 = (f & 15) * 4;
        float4 kv = *(const float4*)&g_k[base + (size_t)r * 512 + c4];
        Ks[r * KV_STRIDE + c4 + 0] = f2tf(kv.x);
        Ks[r * KV_STRIDE + c4 + 1] = f2tf(kv.y);
        Ks[r * KV_STRIDE + c4 + 2] = f2tf(kv.z);
        Ks[r * KV_STRIDE + c4 + 3] = f2tf(kv.w);
        float4 vv = *(const float4*)&g_v[base + (size_t)r * 512 + c4];
        Vs[r * KV_STRIDE + c4 + 0] = f2tf(vv.x);
        Vs[r * KV_STRIDE + c4 + 1] = f2tf(vv.y);
        Vs[r * KV_STRIDE + c4 + 2] = f2tf(vv.z);
        Vs[r * KV_STRIDE + c4 + 3] = f2tf(vv.w);
    }

    int qr0 = warp * 32;
    #pragma unroll
    for (int i = 0; i < 16; i++) {
        int f = lane + i * 32;
        int r = f >> 4, c4 = (f & 15) * 4;
        float4 qv = *(const float4*)&g_q[base + (size_t)(qr0 + r) * 512 + c4];
        Pb[r * P_STRIDE + c4 + 0] = f2tf(qv.x * 0.125f);
        Pb[r * P_STRIDE + c4 + 1] = f2tf(qv.y * 0.125f);
        Pb[r * P_STRIDE + c4 + 2] = f2tf(qv.z * 0.125f);
        Pb[r * P_STRIDE + c4 + 3] = f2tf(qv.w * 0.125f);
    }
    __syncwarp();

    uint32_t q[2][8][4];
    #pragma unroll
    for (int mt = 0; mt < 2; mt++)
        #pragma unroll
        for (int ks = 0; ks < 8; ks++) {
            int r = 16 * mt + g, k0 = 8 * ks;
            q[mt][ks][0] = Pb[r * P_STRIDE + k0 + t];
            q[mt][ks][1] = Pb[(r + 8) * P_STRIDE + k0 + t];
            q[mt][ks][2] = Pb[r * P_STRIDE + k0 + 4 + t];
            q[mt][ks][3] = Pb[(r + 8) * P_STRIDE + k0 + 4 + t];
        }
    __syncthreads();

    float o[2][8][4] = {};
    float den[2][2] = {};

    #pragma unroll 1
    for (int c = 0; c < 4; c++) {
        int kb = c * 64;
        float s[2][8][4] = {};
        #pragma unroll
        for (int ks = 0; ks < 8; ks++) {
            int k0 = 8 * ks;
            uint32_t b[8][2];
            #pragma unroll
            for (int nt = 0; nt < 8; nt++) {
                int kr = kb + 8 * nt + g;
                b[nt][0] = Ks[kr * KV_STRIDE + k0 + t];
                b[nt][1] = Ks[kr * KV_STRIDE + k0 + 4 + t];
            }
            #pragma unroll
            for (int mt = 0; mt < 2; mt++)
                #pragma unroll
                for (int nt = 0; nt < 8; nt++)
                    mma8(s[mt][nt], q[mt][ks], b[nt]);
        }
        #pragma unroll
        for (int mt = 0; mt < 2; mt++) {
            int r = 16 * mt + g;
            #pragma unroll
            for (int nt = 0; nt < 8; nt++) {
                float e0 = __expf(s[mt][nt][0]);
                float e1 = __expf(s[mt][nt][1]);
                float e2 = __expf(s[mt][nt][2]);
                float e3 = __expf(s[mt][nt][3]);
                den[mt][0] += e0 + e1;
                den[mt][1] += e2 + e3;
                int cc = 8 * nt + 2 * t;
                uint2 p0 = {f2tf(e0), f2tf(e1)};
                uint2 p1 = {f2tf(e2), f2tf(e3)};
                *(uint2*)&Pb[r * P_STRIDE + cc] = p0;
                *(uint2*)&Pb[(r + 8) * P_STRIDE + cc] = p1;
            }
        }
        __syncwarp();
        #pragma unroll
        for (int ks = 0; ks < 8; ks++) {
            int k0 = 8 * ks;
            uint32_t pa[2][4], b[8][2];
            #pragma unroll
            for (int mt = 0; mt < 2; mt++) {
                int r = 16 * mt + g;
                pa[mt][0] = Pb[r * P_STRIDE + k0 + t];
                pa[mt][1] = Pb[(r + 8) * P_STRIDE + k0 + t];
                pa[mt][2] = Pb[r * P_STRIDE + k0 + 4 + t];
                pa[mt][3] = Pb[(r + 8) * P_STRIDE + k0 + 4 + t];
            }
            #pragma unroll
            for (int nt = 0; nt < 8; nt++) {
                b[nt][0] = Vs[(kb + k0 + t) * KV_STRIDE + 8 * nt + g];
                b[nt][1] = Vs[(kb + k0 + 4 + t) * KV_STRIDE + 8 * nt + g];
            }
            #pragma unroll
            for (int mt = 0; mt < 2; mt++)
                #pragma unroll
                for (int nt = 0; nt < 8; nt++)
                    mma8(o[mt][nt], pa[mt], b[nt]);
        }
        __syncwarp();
    }

    #pragma unroll
    for (int mt = 0; mt < 2; mt++) {
        float d0 = den[mt][0], d1 = den[mt][1];
        d0 += __shfl_xor_sync(0xffffffffu, d0, 1);
        d0 += __shfl_xor_sync(0xffffffffu, d0, 2);
        d1 += __shfl_xor_sync(0xffffffffu, d1, 1);
        d1 += __shfl_xor_sync(0xffffffffu, d1, 2);
        float inv0 = 1.0f / d0, inv1 = 1.0f / d1;
        int r0 = qr0 + 16 * mt + g;
        #pragma unroll
        for (int nt = 0; nt < 8; nt++) {
            int col = 8 * nt + 2 * t;
            float2 v0 = {o[mt][nt][0] * inv0, o[mt][nt][1] * inv0};
            float2 v1 = {o[mt][nt][2] * inv1, o[mt][nt][3] * inv1};
            *(float2*)&g_ao[base + (size_t)r0 * 512 + col] = v0;
            *(float2*)&g_ao[base + (size_t)(r0 + 8) * 512 + col] = v1;
        }
    }
}

extern "C" void kernel_launch(void* const* d_in, const int* in_sizes, int n_in,
                              void* d_out, int out_size)
{
    const float* query = (const float*)d_in[0];
    const float* key   = (const float*)d_in[1];
    const float* value = (const float*)d_in[2];
    const float* Wq    = (const float*)d_in[3];
    const float* bq    = (const float*)d_in[4];
    const float* Wk    = (const float*)d_in[5];
    const float* bk    = (const float*)d_in[6];
    const float* Wv    = (const float*)d_in[7];
    const float* bv    = (const float*)d_in[8];
    const float* Wo    = (const float*)d_in[9];
    const float* bo    = (const float*)d_in[10];
    float* out = (float*)d_out;

    dim3 gproj(512 / 128, 65536 / 128, 3);
    qkv_proj_kernel<<<gproj, 256>>>(query, key, value, Wq, bq, Wk, bk, Wv, bv);

    cudaFuncSetAttribute(attn_kernel,
                         cudaFuncAttributeMaxDynamicSharedMemorySize, ATTN_SMEM);
    dim3 gattn(8, 256);
    attn_kernel<<<gattn, 256, ATTN_SMEM>>>();

    dim3 gout(512 / 128, 65536 / 128);
    out_proj_kernel<<<gout, 256>>>(Wo, bo, out);
}

// round 8
// speedup vs baseline: 3.7937x; 1.0249x over previous
#include <cuda_runtime.h>
#include <cstdint>

// ---------------- scratch (no cudaMalloc allowed) ----------------
#define ELEMS 33554432
__device__ float g_q[ELEMS];
__device__ float g_k[ELEMS];
__device__ float g_v[ELEMS];
__device__ float g_ao[ELEMS];

// ---------------- helpers ----------------
__device__ __forceinline__ uint32_t f2tf(float x) {
    uint32_t r;
    asm("cvt.rna.tf32.f32 %0, %1;" : "=r"(r) : "f"(x));
    return r;
}

__device__ __forceinline__ void mma8(float* d, const uint32_t* a, const uint32_t* b) {
    asm volatile(
        "mma.sync.aligned.m16n8k8.row.col.f32.tf32.tf32.f32 "
        "{%0,%1,%2,%3}, {%4,%5,%6,%7}, {%8,%9}, {%0,%1,%2,%3};"
        : "+f"(d[0]), "+f"(d[1]), "+f"(d[2]), "+f"(d[3])
        : "r"(a[0]), "r"(a[1]), "r"(a[2]), "r"(a[3]), "r"(b[0]), "r"(b[1]));
}

__device__ __forceinline__ uint32_t smem_u32(const void* p) {
    return (uint32_t)__cvta_generic_to_shared(p);
}
__device__ __forceinline__ void cp16(uint32_t dst, const void* src) {
    asm volatile("cp.async.cg.shared.global [%0], [%1], 16;" :: "r"(dst), "l"(src));
}
__device__ __forceinline__ void cp_commit() {
    asm volatile("cp.async.commit_group;");
}
template <int N>
__device__ __forceinline__ void cp_wait() {
    asm volatile("cp.async.wait_group %0;" :: "n"(N));
}

// ================= projection GEMM (unchanged from round 5) =================
#define AS_STRIDE 20
#define BS_STRIDE 136
#define STAGE_F (128 * AS_STRIDE + 16 * BS_STRIDE)

__device__ __forceinline__ void gemm_body(
    const float* __restrict__ A, const float* __restrict__ W,
    const float* __restrict__ bias, float* __restrict__ C,
    int N, int K)
{
    __shared__ float smem[3 * STAGE_F];

    int tid  = threadIdx.x;
    int lane = tid & 31, warp = tid >> 5;
    int g = lane >> 2, t = lane & 3;
    int wm = (warp & 3) * 32;
    int wn = (warp >> 2) * 64;
    int m0 = blockIdx.y * 128;
    int n0 = blockIdx.x * 128;

    int fa0 = tid, fa1 = tid + 256;
    int ar0 = fa0 >> 2, ac0 = (fa0 & 3) * 4;
    int ar1 = fa1 >> 2, ac1 = (fa1 & 3) * 4;
    int br0 = fa0 >> 5, bc0 = (fa0 & 31) * 4;
    int br1 = fa1 >> 5, bc1 = (fa1 & 31) * 4;

    int nTiles = K / 16;

    auto issue = [&](int tile) {
        if (tile < nTiles) {
            float* st = &smem[(tile % 3) * STAGE_F];
            int kc = tile * 16;
            cp16(smem_u32(&st[ar0 * AS_STRIDE + ac0]),
                 &A[(size_t)(m0 + ar0) * K + kc + ac0]);
            cp16(smem_u32(&st[ar1 * AS_STRIDE + ac1]),
                 &A[(size_t)(m0 + ar1) * K + kc + ac1]);
            float* stb = st + 128 * AS_STRIDE;
            cp16(smem_u32(&stb[br0 * BS_STRIDE + bc0]),
                 &W[(size_t)(kc + br0) * N + n0 + bc0]);
            cp16(smem_u32(&stb[br1 * BS_STRIDE + bc1]),
                 &W[(size_t)(kc + br1) * N + n0 + bc1]);
        }
        cp_commit();
    };

    float acc[2][8][4] = {};

    issue(0);
    issue(1);

    for (int i = 0; i < nTiles; i++) {
        __syncthreads();
        issue(i + 2);
        cp_wait<2>();
        __syncthreads();

        const float* As = &smem[(i % 3) * STAGE_F];
        const float* Bs = As + 128 * AS_STRIDE;

        #pragma unroll
        for (int ks = 0; ks < 2; ks++) {
            int k0 = ks * 8;
            uint32_t a[2][4], b[8][2];
            #pragma unroll
            for (int mt = 0; mt < 2; mt++) {
                int r = wm + 16 * mt + g;
                a[mt][0] = f2tf(As[r * AS_STRIDE + k0 + t]);
                a[mt][1] = f2tf(As[(r + 8) * AS_STRIDE + k0 + t]);
                a[mt][2] = f2tf(As[r * AS_STRIDE + k0 + 4 + t]);
                a[mt][3] = f2tf(As[(r + 8) * AS_STRIDE + k0 + 4 + t]);
            }
            #pragma unroll
            for (int nt = 0; nt < 8; nt++) {
                int cb = wn + 8 * nt + g;
                b[nt][0] = f2tf(Bs[(k0 + t) * BS_STRIDE + cb]);
                b[nt][1] = f2tf(Bs[(k0 + 4 + t) * BS_STRIDE + cb]);
            }
            #pragma unroll
            for (int mt = 0; mt < 2; mt++)
                #pragma unroll
                for (int nt = 0; nt < 8; nt++)
                    mma8(acc[mt][nt], a[mt], b[nt]);
        }
    }

    #pragma unroll
    for (int mt = 0; mt < 2; mt++) {
        int r0 = m0 + wm + 16 * mt + g;
        #pragma unroll
        for (int nt = 0; nt < 8; nt++) {
            int col = n0 + wn + 8 * nt + 2 * t;
            float b0 = bias[col], b1 = bias[col + 1];
            float2 v0 = {acc[mt][nt][0] + b0, acc[mt][nt][1] + b1};
            float2 v1 = {acc[mt][nt][2] + b0, acc[mt][nt][3] + b1};
            *(float2*)&C[(size_t)r0 * N + col] = v0;
            *(float2*)&C[(size_t)(r0 + 8) * N + col] = v1;
        }
    }
}

__global__ __launch_bounds__(256, 2) void qkv_proj_kernel(
    const float* __restrict__ qin, const float* __restrict__ kin,
    const float* __restrict__ vin,
    const float* __restrict__ Wq, const float* __restrict__ bq,
    const float* __restrict__ Wk, const float* __restrict__ bk,
    const float* __restrict__ Wv, const float* __restrict__ bv)
{
    const float* A; const float* W; const float* bias; float* C;
    if (blockIdx.z == 0)      { A = qin; W = Wq; bias = bq; C = g_q; }
    else if (blockIdx.z == 1) { A = kin; W = Wk; bias = bk; C = g_k; }
    else                      { A = vin; W = Wv; bias = bv; C = g_v; }
    gemm_body(A, W, bias, C, 512, 128);
}

__global__ __launch_bounds__(256, 2) void out_proj_kernel(
    const float* __restrict__ Wo, const float* __restrict__ bo,
    float* __restrict__ out)
{
    gemm_body(g_ao, Wo, bo, out, 512, 512);
}

// ================= attention: flash-pipelined, 2 CTAs per (bn,h) ============
// grid (8, 256, 2): h, bn, row-half. 256 threads = 8 warps x 16 q-rows.
// K chunks (64 keys) double-buffered via cp.async, raw f32, cvt at frag load.
// Strides: K=68 (bank-conflict-free for K-pattern), V=72 (free for V-pattern).
#define KS_STRIDE 68
#define VS_STRIDE 72
#define PB_STRIDE 68
#define K_STAGE_F (64 * KS_STRIDE)        // 4352 floats
#define V_STAGE_F (64 * VS_STRIDE)        // 4608 floats
#define ATTN_SMEM ((2 * K_STAGE_F + 2 * V_STAGE_F + 8 * 16 * PB_STRIDE) * 4) // 106496 B

__global__ __launch_bounds__(256, 2) void attn_kernel()
{
    extern __shared__ float sm[];
    float* Kst = sm;                              // [2][64][KS_STRIDE]
    float* Vst = sm + 2 * K_STAGE_F;              // [2][64][VS_STRIDE]
    float* PbA = sm + 2 * K_STAGE_F + 2 * V_STAGE_F;

    int tid = threadIdx.x, lane = tid & 31, warp = tid >> 5;
    int g = lane >> 2, t = lane & 3;
    uint32_t* Pb = (uint32_t*)(PbA + warp * (16 * PB_STRIDE));

    int h  = blockIdx.x;                 // 0..7
    int bn = blockIdx.y;                 // 0..255
    int half = blockIdx.z;               // 0..1
    size_t base  = (size_t)bn * 131072 + (size_t)h * 64;          // K/V rows
    size_t baseq = base + (size_t)half * 128 * 512;               // Q rows

    // per-thread cp.async slots for a 64x64 chunk (1024 float4 per tensor)
    int f0 = tid, f1 = tid + 256, f2 = tid + 512, f3 = tid + 768;
    int r0 = f0 >> 4, c0 = (f0 & 15) * 4;
    int r1 = f1 >> 4, c1 = (f1 & 15) * 4;
    int r2 = f2 >> 4, c2 = (f2 & 15) * 4;
    int r3 = f3 >> 4, c3 = (f3 & 15) * 4;

    auto issue = [&](int chunk) {
        if (chunk < 4) {
            int kb = chunk * 64;
            float* Kd = Kst + (chunk & 1) * K_STAGE_F;
            float* Vd = Vst + (chunk & 1) * V_STAGE_F;
            cp16(smem_u32(&Kd[r0 * KS_STRIDE + c0]), &g_k[base + (size_t)(kb + r0) * 512 + c0]);
            cp16(smem_u32(&Kd[r1 * KS_STRIDE + c1]), &g_k[base + (size_t)(kb + r1) * 512 + c1]);
            cp16(smem_u32(&Kd[r2 * KS_STRIDE + c2]), &g_k[base + (size_t)(kb + r2) * 512 + c2]);
            cp16(smem_u32(&Kd[r3 * KS_STRIDE + c3]), &g_k[base + (size_t)(kb + r3) * 512 + c3]);
            cp16(smem_u32(&Vd[r0 * VS_STRIDE + c0]), &g_v[base + (size_t)(kb + r0) * 512 + c0]);
            cp16(smem_u32(&Vd[r1 * VS_STRIDE + c1]), &g_v[base + (size_t)(kb + r1) * 512 + c1]);
            cp16(smem_u32(&Vd[r2 * VS_STRIDE + c2]), &g_v[base + (size_t)(kb + r2) * 512 + c2]);
            cp16(smem_u32(&Vd[r3 * VS_STRIDE + c3]), &g_v[base + (size_t)(kb + r3) * 512 + c3]);
        }
        cp_commit();
    };

    issue(0);
    issue(1);

    // Q tile: warp's 16 rows x 64 cols, scaled, -> Pb -> frags
    int qr0 = warp * 16;
    #pragma unroll
    for (int i = 0; i < 8; i++) {
        int f = lane + i * 32;           // 256 float4 slots
        int r = f >> 4, c4 = (f & 15) * 4;
        float4 qv = *(const float4*)&g_q[baseq + (size_t)(qr0 + r) * 512 + c4];
        Pb[r * PB_STRIDE + c4 + 0] = f2tf(qv.x * 0.125f);
        Pb[r * PB_STRIDE + c4 + 1] = f2tf(qv.y * 0.125f);
        Pb[r * PB_STRIDE + c4 + 2] = f2tf(qv.z * 0.125f);
        Pb[r * PB_STRIDE + c4 + 3] = f2tf(qv.w * 0.125f);
    }
    __syncwarp();

    uint32_t q[8][4];
    #pragma unroll
    for (int ks = 0; ks < 8; ks++) {
        int k0 = 8 * ks;
        q[ks][0] = Pb[g * PB_STRIDE + k0 + t];
        q[ks][1] = Pb[(g + 8) * PB_STRIDE + k0 + t];
        q[ks][2] = Pb[g * PB_STRIDE + k0 + 4 + t];
        q[ks][3] = Pb[(g + 8) * PB_STRIDE + k0 + 4 + t];
    }
    __syncwarp();

    float o[8][4] = {};
    float den0 = 0.0f, den1 = 0.0f;

    #pragma unroll 1
    for (int c = 0; c < 4; c++) {
        cp_wait<1>();
        __syncthreads();                  // chunk c resident, all warps see it
        const float* Ks = Kst + (c & 1) * K_STAGE_F;
        const float* Vs = Vst + (c & 1) * V_STAGE_F;

        // ---- S = Q K_chunk^T ----
        float s[8][4] = {};
        #pragma unroll
        for (int ks = 0; ks < 8; ks++) {
            int k0 = 8 * ks;
            uint32_t b[8][2];
            #pragma unroll
            for (int nt = 0; nt < 8; nt++) {
                int kr = 8 * nt + g;
                b[nt][0] = f2tf(Ks[kr * KS_STRIDE + k0 + t]);
                b[nt][1] = f2tf(Ks[kr * KS_STRIDE + k0 + 4 + t]);
            }
            #pragma unroll
            for (int nt = 0; nt < 8; nt++)
                mma8(s[nt], q[ks], b[nt]);
        }

        // ---- exp, denom, P -> Pb ----
        #pragma unroll
        for (int nt = 0; nt < 8; nt++) {
            float e0 = __expf(s[nt][0]);
            float e1 = __expf(s[nt][1]);
            float e2 = __expf(s[nt][2]);
            float e3 = __expf(s[nt][3]);
            den0 += e0 + e1;
            den1 += e2 + e3;
            int cc = 8 * nt + 2 * t;
            uint2 p0 = {f2tf(e0), f2tf(e1)};
            uint2 p1 = {f2tf(e2), f2tf(e3)};
            *(uint2*)&Pb[g * PB_STRIDE + cc] = p0;
            *(uint2*)&Pb[(g + 8) * PB_STRIDE + cc] = p1;
        }
        __syncwarp();

        // ---- O += P V_chunk ----
        #pragma unroll
        for (int ks = 0; ks < 8; ks++) {
            int k0 = 8 * ks;
            uint32_t pa[4], b[8][2];
            pa[0] = Pb[g * PB_STRIDE + k0 + t];
            pa[1] = Pb[(g + 8) * PB_STRIDE + k0 + t];
            pa[2] = Pb[g * PB_STRIDE + k0 + 4 + t];
            pa[3] = Pb[(g + 8) * PB_STRIDE + k0 + 4 + t];
            #pragma unroll
            for (int nt = 0; nt < 8; nt++) {
                b[nt][0] = f2tf(Vs[(k0 + t) * VS_STRIDE + 8 * nt + g]);
                b[nt][1] = f2tf(Vs[(k0 + 4 + t) * VS_STRIDE + 8 * nt + g]);
            }
            #pragma unroll
            for (int nt = 0; nt < 8; nt++)
                mma8(o[nt], pa, b[nt]);
        }

        __syncthreads();                  // all warps done with stage (c&1)
        issue(c + 2);                     // refill it
    }

    // ---- normalize, store ----
    den0 += __shfl_xor_sync(0xffffffffu, den0, 1);
    den0 += __shfl_xor_sync(0xffffffffu, den0, 2);
    den1 += __shfl_xor_sync(0xffffffffu, den1, 1);
    den1 += __shfl_xor_sync(0xffffffffu, den1, 2);
    float inv0 = 1.0f / den0, inv1 = 1.0f / den1;

    int rg = qr0 + g;
    #pragma unroll
    for (int nt = 0; nt < 8; nt++) {
        int col = 8 * nt + 2 * t;
        float2 v0 = {o[nt][0] * inv0, o[nt][1] * inv0};
        float2 v1 = {o[nt][2] * inv1, o[nt][3] * inv1};
        *(float2*)&g_ao[baseq + (size_t)rg * 512 + col] = v0;
        *(float2*)&g_ao[baseq + (size_t)(rg + 8) * 512 + col] = v1;
    }
}

extern "C" void kernel_launch(void* const* d_in, const int* in_sizes, int n_in,
                              void* d_out, int out_size)
{
    const float* query = (const float*)d_in[0];
    const float* key   = (const float*)d_in[1];
    const float* value = (const float*)d_in[2];
    const float* Wq    = (const float*)d_in[3];
    const float* bq    = (const float*)d_in[4];
    const float* Wk    = (const float*)d_in[5];
    const float* bk    = (const float*)d_in[6];
    const float* Wv    = (const float*)d_in[7];
    const float* bv    = (const float*)d_in[8];
    const float* Wo    = (const float*)d_in[9];
    const float* bo    = (const float*)d_in[10];
    float* out = (float*)d_out;

    dim3 gproj(512 / 128, 65536 / 128, 3);
    qkv_proj_kernel<<<gproj, 256>>>(query, key, value, Wq, bq, Wk, bk, Wv, bv);

    cudaFuncSetAttribute(attn_kernel,
                         cudaFuncAttributeMaxDynamicSharedMemorySize, ATTN_SMEM);
    dim3 gattn(8, 256, 2);
    attn_kernel<<<gattn, 256, ATTN_SMEM>>>();

    dim3 gout(512 / 128, 65536 / 128);
    out_proj_kernel<<<gout, 256>>>(Wo, bo, out);
}

// round 10
// speedup vs baseline: 4.3036x; 1.1344x over previous
#include <cuda_runtime.h>
#include <cstdint>

// ---------------- scratch (no cudaMalloc allowed) ----------------
#define ELEMS 33554432
__device__ float g_q[ELEMS];
__device__ float g_k[ELEMS];
__device__ float g_v[ELEMS];
__device__ float g_ao[ELEMS];
// pre-rounded tf32 weights
__device__ float g_wq[65536];
__device__ float g_wk[65536];
__device__ float g_wv[65536];
__device__ float g_wo[262144];

// ---------------- helpers ----------------
__device__ __forceinline__ uint32_t f2tf(float x) {
    uint32_t r;
    asm("cvt.rna.tf32.f32 %0, %1;" : "=r"(r) : "f"(x));
    return r;
}
__device__ __forceinline__ float f2tf_f(float x) {
    return __uint_as_float(f2tf(x));
}

__device__ __forceinline__ void mma8(float* d, const uint32_t* a, const uint32_t* b) {
    asm volatile(
        "mma.sync.aligned.m16n8k8.row.col.f32.tf32.tf32.f32 "
        "{%0,%1,%2,%3}, {%4,%5,%6,%7}, {%8,%9}, {%0,%1,%2,%3};"
        : "+f"(d[0]), "+f"(d[1]), "+f"(d[2]), "+f"(d[3])
        : "r"(a[0]), "r"(a[1]), "r"(a[2]), "r"(a[3]), "r"(b[0]), "r"(b[1]));
}

__device__ __forceinline__ uint32_t smem_u32(const void* p) {
    return (uint32_t)__cvta_generic_to_shared(p);
}
__device__ __forceinline__ void cp16(uint32_t dst, const void* src) {
    asm volatile("cp.async.cg.shared.global [%0], [%1], 16;" :: "r"(dst), "l"(src));
}
__device__ __forceinline__ void cp_commit() {
    asm volatile("cp.async.commit_group;");
}
template <int N>
__device__ __forceinline__ void cp_wait() {
    asm volatile("cp.async.wait_group %0;" :: "n"(N));
}

// ---------------- weight prep: round to tf32 once ----------------
__global__ void prep_weights_kernel(
    const float* __restrict__ Wq, const float* __restrict__ Wk,
    const float* __restrict__ Wv, const float* __restrict__ Wo)
{
    int i = blockIdx.x * 256 + threadIdx.x;     // 0..262143
    if (i < 65536) {
        g_wq[i] = f2tf_f(Wq[i]);
        g_wk[i] = f2tf_f(Wk[i]);
        g_wv[i] = f2tf_f(Wv[i]);
    }
    g_wo[i] = f2tf_f(Wo[i]);
}

// ================= projection GEMM: C = A @ W + bias ========================
// block tile 128x128, BK=16, 3-stage cp.async, 1 sync per tile.
// W is pre-rounded tf32 (raw frag loads); A converted iff CVT_A.
// Output C stored tf32-rounded iff ROUND_OUT.
#define AS_STRIDE 20
#define BS_STRIDE 136
#define STAGE_F (128 * AS_STRIDE + 16 * BS_STRIDE)

template <bool CVT_A, bool ROUND_OUT>
__device__ __forceinline__ void gemm_body(
    const float* __restrict__ A, const float* __restrict__ W,
    const float* __restrict__ bias, float* __restrict__ C,
    int N, int K)
{
    __shared__ float smem[3 * STAGE_F];

    int tid  = threadIdx.x;
    int lane = tid & 31, warp = tid >> 5;
    int g = lane >> 2, t = lane & 3;
    int wm = (warp & 3) * 32;
    int wn = (warp >> 2) * 64;
    int m0 = blockIdx.y * 128;
    int n0 = blockIdx.x * 128;

    int fa0 = tid, fa1 = tid + 256;
    int ar0 = fa0 >> 2, ac0 = (fa0 & 3) * 4;
    int ar1 = fa1 >> 2, ac1 = (fa1 & 3) * 4;
    int br0 = fa0 >> 5, bc0 = (fa0 & 31) * 4;
    int br1 = fa1 >> 5, bc1 = (fa1 & 31) * 4;

    int nTiles = K / 16;

    auto issue = [&](int tile) {
        if (tile < nTiles) {
            float* st = &smem[(tile % 3) * STAGE_F];
            int kc = tile * 16;
            cp16(smem_u32(&st[ar0 * AS_STRIDE + ac0]),
                 &A[(size_t)(m0 + ar0) * K + kc + ac0]);
            cp16(smem_u32(&st[ar1 * AS_STRIDE + ac1]),
                 &A[(size_t)(m0 + ar1) * K + kc + ac1]);
            float* stb = st + 128 * AS_STRIDE;
            cp16(smem_u32(&stb[br0 * BS_STRIDE + bc0]),
                 &W[(size_t)(kc + br0) * N + n0 + bc0]);
            cp16(smem_u32(&stb[br1 * BS_STRIDE + bc1]),
                 &W[(size_t)(kc + br1) * N + n0 + bc1]);
        }
        cp_commit();
    };

    float acc[2][8][4] = {};

    issue(0);
    issue(1);

    for (int i = 0; i < nTiles; i++) {
        cp_wait<1>();             // tile i resident
        __syncthreads();          // everyone sees it; compute(i-1) done by all

        const float* As = &smem[(i % 3) * STAGE_F];
        const float* Bs = As + 128 * AS_STRIDE;

        #pragma unroll
        for (int ks = 0; ks < 2; ks++) {
            int k0 = ks * 8;
            uint32_t a[2][4], b[8][2];
            #pragma unroll
            for (int mt = 0; mt < 2; mt++) {
                int r = wm + 16 * mt + g;
                if (CVT_A) {
                    a[mt][0] = f2tf(As[r * AS_STRIDE + k0 + t]);
                    a[mt][1] = f2tf(As[(r + 8) * AS_STRIDE + k0 + t]);
                    a[mt][2] = f2tf(As[r * AS_STRIDE + k0 + 4 + t]);
                    a[mt][3] = f2tf(As[(r + 8) * AS_STRIDE + k0 + 4 + t]);
                } else {
                    a[mt][0] = __float_as_uint(As[r * AS_STRIDE + k0 + t]);
                    a[mt][1] = __float_as_uint(As[(r + 8) * AS_STRIDE + k0 + t]);
                    a[mt][2] = __float_as_uint(As[r * AS_STRIDE + k0 + 4 + t]);
                    a[mt][3] = __float_as_uint(As[(r + 8) * AS_STRIDE + k0 + 4 + t]);
                }
            }
            #pragma unroll
            for (int nt = 0; nt < 8; nt++) {
                int cb = wn + 8 * nt + g;
                b[nt][0] = __float_as_uint(Bs[(k0 + t) * BS_STRIDE + cb]);
                b[nt][1] = __float_as_uint(Bs[(k0 + 4 + t) * BS_STRIDE + cb]);
            }
            #pragma unroll
            for (int mt = 0; mt < 2; mt++)
                #pragma unroll
                for (int nt = 0; nt < 8; nt++)
                    mma8(acc[mt][nt], a[mt], b[nt]);
        }

        issue(i + 2);             // overwrites stage (i-1): safe after the sync
    }

    #pragma unroll
    for (int mt = 0; mt < 2; mt++) {
        int r0 = m0 + wm + 16 * mt + g;
        #pragma unroll
        for (int nt = 0; nt < 8; nt++) {
            int col = n0 + wn + 8 * nt + 2 * t;
            float b0 = bias[col], b1 = bias[col + 1];
            float2 v0, v1;
            if (ROUND_OUT) {
                v0 = {f2tf_f(acc[mt][nt][0] + b0), f2tf_f(acc[mt][nt][1] + b1)};
                v1 = {f2tf_f(acc[mt][nt][2] + b0), f2tf_f(acc[mt][nt][3] + b1)};
            } else {
                v0 = {acc[mt][nt][0] + b0, acc[mt][nt][1] + b1};
                v1 = {acc[mt][nt][2] + b0, acc[mt][nt][3] + b1};
            }
            *(float2*)&C[(size_t)r0 * N + col] = v0;
            *(float2*)&C[(size_t)(r0 + 8) * N + col] = v1;
        }
    }
}

__global__ __launch_bounds__(256, 2) void qkv_proj_kernel(
    const float* __restrict__ qin, const float* __restrict__ kin,
    const float* __restrict__ vin,
    const float* __restrict__ bq, const float* __restrict__ bk,
    const float* __restrict__ bv)
{
    const float* A; const float* W; const float* bias; float* C;
    if (blockIdx.z == 0)      { A = qin; W = g_wq; bias = bq; C = g_q; }
    else if (blockIdx.z == 1) { A = kin; W = g_wk; bias = bk; C = g_k; }
    else                      { A = vin; W = g_wv; bias = bv; C = g_v; }
    gemm_body<true, true>(A, W, bias, C, 512, 128);
}

__global__ __launch_bounds__(256, 2) void out_proj_kernel(
    const float* __restrict__ bo, float* __restrict__ out)
{
    gemm_body<false, false>(g_ao, g_wo, bo, out, 512, 512);
}

// ================= attention: flash-pipelined, 2 CTAs per (bn,h) ============
// All operands arrive pre-rounded tf32 -> zero cvt in the mainloop.
#define KS_STRIDE 68
#define VS_STRIDE 72
#define PB_STRIDE 68
#define K_STAGE_F (64 * KS_STRIDE)
#define V_STAGE_F (64 * VS_STRIDE)
#define ATTN_SMEM ((2 * K_STAGE_F + 2 * V_STAGE_F + 8 * 16 * PB_STRIDE) * 4) // 106496 B

__global__ __launch_bounds__(256, 2) void attn_kernel()
{
    extern __shared__ float sm[];
    float* Kst = sm;
    float* Vst = sm + 2 * K_STAGE_F;
    float* PbA = sm + 2 * K_STAGE_F + 2 * V_STAGE_F;

    int tid = threadIdx.x, lane = tid & 31, warp = tid >> 5;
    int g = lane >> 2, t = lane & 3;
    uint32_t* Pb = (uint32_t*)(PbA + warp * (16 * PB_STRIDE));

    int h  = blockIdx.x;
    int bn = blockIdx.y;
    int half = blockIdx.z;
    size_t base  = (size_t)bn * 131072 + (size_t)h * 64;
    size_t baseq = base + (size_t)half * 128 * 512;

    int f0 = tid, f1 = tid + 256, f2 = tid + 512, f3 = tid + 768;
    int r0 = f0 >> 4, c0 = (f0 & 15) * 4;
    int r1 = f1 >> 4, c1 = (f1 & 15) * 4;
    int r2 = f2 >> 4, c2 = (f2 & 15) * 4;
    int r3 = f3 >> 4, c3 = (f3 & 15) * 4;

    auto issue = [&](int chunk) {
        if (chunk < 4) {
            int kb = chunk * 64;
            float* Kd = Kst + (chunk & 1) * K_STAGE_F;
            float* Vd = Vst + (chunk & 1) * V_STAGE_F;
            cp16(smem_u32(&Kd[r0 * KS_STRIDE + c0]), &g_k[base + (size_t)(kb + r0) * 512 + c0]);
            cp16(smem_u32(&Kd[r1 * KS_STRIDE + c1]), &g_k[base + (size_t)(kb + r1) * 512 + c1]);
            cp16(smem_u32(&Kd[r2 * KS_STRIDE + c2]), &g_k[base + (size_t)(kb + r2) * 512 + c2]);
            cp16(smem_u32(&Kd[r3 * KS_STRIDE + c3]), &g_k[base + (size_t)(kb + r3) * 512 + c3]);
            cp16(smem_u32(&Vd[r0 * VS_STRIDE + c0]), &g_v[base + (size_t)(kb + r0) * 512 + c0]);
            cp16(smem_u32(&Vd[r1 * VS_STRIDE + c1]), &g_v[base + (size_t)(kb + r1) * 512 + c1]);
            cp16(smem_u32(&Vd[r2 * VS_STRIDE + c2]), &g_v[base + (size_t)(kb + r2) * 512 + c2]);
            cp16(smem_u32(&Vd[r3 * VS_STRIDE + c3]), &g_v[base + (size_t)(kb + r3) * 512 + c3]);
        }
        cp_commit();
    };

    issue(0);
    issue(1);

    // Q tile: warp's 16 rows x 64 cols; g_q pre-rounded, *0.125 is exact
    int qr0 = warp * 16;
    #pragma unroll
    for (int i = 0; i < 8; i++) {
        int f = lane + i * 32;
        int r = f >> 4, c4 = (f & 15) * 4;
        float4 qv = *(const float4*)&g_q[baseq + (size_t)(qr0 + r) * 512 + c4];
        Pb[r * PB_STRIDE + c4 + 0] = __float_as_uint(qv.x * 0.125f);
        Pb[r * PB_STRIDE + c4 + 1] = __float_as_uint(qv.y * 0.125f);
        Pb[r * PB_STRIDE + c4 + 2] = __float_as_uint(qv.z * 0.125f);
        Pb[r * PB_STRIDE + c4 + 3] = __float_as_uint(qv.w * 0.125f);
    }
    __syncwarp();

    uint32_t q[8][4];
    #pragma unroll
    for (int ks = 0; ks < 8; ks++) {
        int k0 = 8 * ks;
        q[ks][0] = Pb[g * PB_STRIDE + k0 + t];
        q[ks][1] = Pb[(g + 8) * PB_STRIDE + k0 + t];
        q[ks][2] = Pb[g * PB_STRIDE + k0 + 4 + t];
        q[ks][3] = Pb[(g + 8) * PB_STRIDE + k0 + 4 + t];
    }
    __syncwarp();

    float o[8][4] = {};
    float den0 = 0.0f, den1 = 0.0f;

    #pragma unroll 1
    for (int c = 0; c < 4; c++) {
        cp_wait<1>();
        __syncthreads();
        const float* Ks = Kst + (c & 1) * K_STAGE_F;
        const float* Vs = Vst + (c & 1) * V_STAGE_F;

        // ---- S = Q K_chunk^T ----
        float s[8][4] = {};
        #pragma unroll
        for (int ks = 0; ks < 8; ks++) {
            int k0 = 8 * ks;
            uint32_t b[8][2];
            #pragma unroll
            for (int nt = 0; nt < 8; nt++) {
                int kr = 8 * nt + g;
                b[nt][0] = __float_as_uint(Ks[kr * KS_STRIDE + k0 + t]);
                b[nt][1] = __float_as_uint(Ks[kr * KS_STRIDE + k0 + 4 + t]);
            }
            #pragma unroll
            for (int nt = 0; nt < 8; nt++)
                mma8(s[nt], q[ks], b[nt]);
        }

        // ---- exp, denom, P -> Pb ----
        #pragma unroll
        for (int nt = 0; nt < 8; nt++) {
            float e0 = __expf(s[nt][0]);
            float e1 = __expf(s[nt][1]);
            float e2 = __expf(s[nt][2]);
            float e3 = __expf(s[nt][3]);
            den0 += e0 + e1;
            den1 += e2 + e3;
            int cc = 8 * nt + 2 * t;
            uint2 p0 = {f2tf(e0), f2tf(e1)};
            uint2 p1 = {f2tf(e2), f2tf(e3)};
            *(uint2*)&Pb[g * PB_STRIDE + cc] = p0;
            *(uint2*)&Pb[(g + 8) * PB_STRIDE + cc] = p1;
        }
        __syncwarp();

        // ---- O += P V_chunk ----
        #pragma unroll
        for (int ks = 0; ks < 8; ks++) {
            int k0 = 8 * ks;
            uint32_t pa[4], b[8][2];
            pa[0] = Pb[g * PB_STRIDE + k0 + t];
            pa[1] = Pb[(g + 8) * PB_STRIDE + k0 + t];
            pa[2] = Pb[g * PB_STRIDE + k0 + 4 + t];
            pa[3] = Pb[(g + 8) * PB_STRIDE + k0 + 4 + t];
            #pragma unroll
            for (int nt = 0; nt < 8; nt++) {
                b[nt][0] = __float_as_uint(Vs[(k0 + t) * VS_STRIDE + 8 * nt + g]);
                b[nt][1] = __float_as_uint(Vs[(k0 + 4 + t) * VS_STRIDE + 8 * nt + g]);
            }
            #pragma unroll
            for (int nt = 0; nt < 8; nt++)
                mma8(o[nt], pa, b[nt]);
        }

        __syncthreads();
        issue(c + 2);
    }

    // ---- normalize, store tf32-rounded (consumed by out_proj raw) ----
    den0 += __shfl_xor_sync(0xffffffffu, den0, 1);
    den0 += __shfl_xor_sync(0xffffffffu, den0, 2);
    den1 += __shfl_xor_sync(0xffffffffu, den1, 1);
    den1 += __shfl_xor_sync(0xffffffffu, den1, 2);
    float inv0 = 1.0f / den0, inv1 = 1.0f / den1;

    int rg = qr0 + g;
    #pragma unroll
    for (int nt = 0; nt < 8; nt++) {
        int col = 8 * nt + 2 * t;
        float2 v0 = {f2tf_f(o[nt][0] * inv0), f2tf_f(o[nt][1] * inv0)};
        float2 v1 = {f2tf_f(o[nt][2] * inv1), f2tf_f(o[nt][3] * inv1)};
        *(float2*)&g_ao[baseq + (size_t)rg * 512 + col] = v0;
        *(float2*)&g_ao[baseq + (size_t)(rg + 8) * 512 + col] = v1;
    }
}

extern "C" void kernel_launch(void* const* d_in, const int* in_sizes, int n_in,
                              void* d_out, int out_size)
{
    const float* query = (const float*)d_in[0];
    const float* key   = (const float*)d_in[1];
    const float* value = (const float*)d_in[2];
    const float* Wq    = (const float*)d_in[3];
    const float* bq    = (const float*)d_in[4];
    const float* Wk    = (const float*)d_in[5];
    const float* bk    = (const float*)d_in[6];
    const float* Wv    = (const float*)d_in[7];
    const float* bv    = (const float*)d_in[8];
    const float* Wo    = (const float*)d_in[9];
    const float* bo    = (const float*)d_in[10];
    float* out = (float*)d_out;

    prep_weights_kernel<<<1024, 256>>>(Wq, Wk, Wv, Wo);

    dim3 gproj(512 / 128, 65536 / 128, 3);
    qkv_proj_kernel<<<gproj, 256>>>(query, key, value, bq, bk, bv);

    cudaFuncSetAttribute(attn_kernel,
                         cudaFuncAttributeMaxDynamicSharedMemorySize, ATTN_SMEM);
    dim3 gattn(8, 256, 2);
    attn_kernel<<<gattn, 256, ATTN_SMEM>>>();

    dim3 gout(512 / 128, 65536 / 128);
    out_proj_kernel<<<gout, 256>>>(bo, out);
}

// round 11
// speedup vs baseline: 4.3052x; 1.0004x over previous
#include <cuda_runtime.h>
#include <cstdint>

// ---------------- scratch (no cudaMalloc allowed) ----------------
#define ELEMS 33554432
__device__ float g_q[ELEMS];
__device__ float g_k[ELEMS];
__device__ float g_v[ELEMS];
__device__ float g_ao[ELEMS];
// pre-rounded tf32 weights
__device__ float g_wq[65536];
__device__ float g_wk[65536];
__device__ float g_wv[65536];
__device__ float g_wo[262144];

// ---------------- helpers ----------------
__device__ __forceinline__ uint32_t f2tf(float x) {
    uint32_t r;
    asm("cvt.rna.tf32.f32 %0, %1;" : "=r"(r) : "f"(x));
    return r;
}
__device__ __forceinline__ float f2tf_f(float x) {
    return __uint_as_float(f2tf(x));
}

__device__ __forceinline__ void mma8(float* d, const uint32_t* a, const uint32_t* b) {
    asm volatile(
        "mma.sync.aligned.m16n8k8.row.col.f32.tf32.tf32.f32 "
        "{%0,%1,%2,%3}, {%4,%5,%6,%7}, {%8,%9}, {%0,%1,%2,%3};"
        : "+f"(d[0]), "+f"(d[1]), "+f"(d[2]), "+f"(d[3])
        : "r"(a[0]), "r"(a[1]), "r"(a[2]), "r"(a[3]), "r"(b[0]), "r"(b[1]));
}

__device__ __forceinline__ uint32_t smem_u32(const void* p) {
    return (uint32_t)__cvta_generic_to_shared(p);
}
__device__ __forceinline__ void cp16(uint32_t dst, const void* src) {
    asm volatile("cp.async.cg.shared.global [%0], [%1], 16;" :: "r"(dst), "l"(src));
}
__device__ __forceinline__ void cp_commit() {
    asm volatile("cp.async.commit_group;");
}
template <int N>
__device__ __forceinline__ void cp_wait() {
    asm volatile("cp.async.wait_group %0;" :: "n"(N));
}

// ---------------- weight prep: round to tf32 once ----------------
__global__ void prep_weights_kernel(
    const float* __restrict__ Wq, const float* __restrict__ Wk,
    const float* __restrict__ Wv, const float* __restrict__ Wo)
{
    int i = blockIdx.x * 256 + threadIdx.x;     // 0..262143
    if (i < 65536) {
        g_wq[i] = f2tf_f(Wq[i]);
        g_wk[i] = f2tf_f(Wk[i]);
        g_wv[i] = f2tf_f(Wv[i]);
    }
    g_wo[i] = f2tf_f(Wo[i]);
}

// ================= projection GEMM: C = A @ W + bias ========================
// CTA tile 128x128, 128 threads = 4 warps, warp tile 64x64 (2x2 warp grid).
// BK=16, 3-stage cp.async pipeline, 1 sync per tile.
// 64x64 warp tile: 32 LDS per 32 MMAs per k-step (128 B/mma crossbar traffic).
#define AS_STRIDE 20
#define BS_STRIDE 136
#define STAGE_F (128 * AS_STRIDE + 16 * BS_STRIDE)

template <bool CVT_A, bool ROUND_OUT>
__device__ __forceinline__ void gemm_body(
    const float* __restrict__ A, const float* __restrict__ W,
    const float* __restrict__ bias, float* __restrict__ C,
    int N, int K)
{
    __shared__ float smem[3 * STAGE_F];

    int tid  = threadIdx.x;
    int lane = tid & 31, warp = tid >> 5;   // warp 0..3
    int g = lane >> 2, t = lane & 3;
    int wm = (warp & 1) * 64;               // warp row base
    int wn = (warp >> 1) * 64;              // warp col base
    int m0 = blockIdx.y * 128;
    int n0 = blockIdx.x * 128;

    // per-thread cp.async slots: 4 A chunks + 4 B chunks (128 threads)
    int ar[4], ac[4], br[4], bc[4];
    #pragma unroll
    for (int i = 0; i < 4; i++) {
        int f = tid + i * 128;              // 0..511 float4 slots
        ar[i] = f >> 2; ac[i] = (f & 3) * 4;
        br[i] = f >> 5; bc[i] = (f & 31) * 4;
    }

    int nTiles = K / 16;

    auto issue = [&](int tile) {
        if (tile < nTiles) {
            float* st = &smem[(tile % 3) * STAGE_F];
            float* stb = st + 128 * AS_STRIDE;
            int kc = tile * 16;
            #pragma unroll
            for (int i = 0; i < 4; i++)
                cp16(smem_u32(&st[ar[i] * AS_STRIDE + ac[i]]),
                     &A[(size_t)(m0 + ar[i]) * K + kc + ac[i]]);
            #pragma unroll
            for (int i = 0; i < 4; i++)
                cp16(smem_u32(&stb[br[i] * BS_STRIDE + bc[i]]),
                     &W[(size_t)(kc + br[i]) * N + n0 + bc[i]]);
        }
        cp_commit();
    };

    float acc[4][8][4] = {};

    issue(0);
    issue(1);

    for (int i = 0; i < nTiles; i++) {
        cp_wait<1>();             // tile i resident
        __syncthreads();          // visible to all; compute(i-1) done by all

        const float* As = &smem[(i % 3) * STAGE_F];
        const float* Bs = As + 128 * AS_STRIDE;

        #pragma unroll
        for (int ks = 0; ks < 2; ks++) {
            int k0 = ks * 8;
            uint32_t a[4][4], b[8][2];
            #pragma unroll
            for (int mt = 0; mt < 4; mt++) {
                int r = wm + 16 * mt + g;
                if (CVT_A) {
                    a[mt][0] = f2tf(As[r * AS_STRIDE + k0 + t]);
                    a[mt][1] = f2tf(As[(r + 8) * AS_STRIDE + k0 + t]);
                    a[mt][2] = f2tf(As[r * AS_STRIDE + k0 + 4 + t]);
                    a[mt][3] = f2tf(As[(r + 8) * AS_STRIDE + k0 + 4 + t]);
                } else {
                    a[mt][0] = __float_as_uint(As[r * AS_STRIDE + k0 + t]);
                    a[mt][1] = __float_as_uint(As[(r + 8) * AS_STRIDE + k0 + t]);
                    a[mt][2] = __float_as_uint(As[r * AS_STRIDE + k0 + 4 + t]);
                    a[mt][3] = __float_as_uint(As[(r + 8) * AS_STRIDE + k0 + 4 + t]);
                }
            }
            #pragma unroll
            for (int nt = 0; nt < 8; nt++) {
                int cb = wn + 8 * nt + g;
                b[nt][0] = __float_as_uint(Bs[(k0 + t) * BS_STRIDE + cb]);
                b[nt][1] = __float_as_uint(Bs[(k0 + 4 + t) * BS_STRIDE + cb]);
            }
            #pragma unroll
            for (int mt = 0; mt < 4; mt++)
                #pragma unroll
                for (int nt = 0; nt < 8; nt++)
                    mma8(acc[mt][nt], a[mt], b[nt]);
        }

        issue(i + 2);             // overwrites stage (i-1): safe after the sync
    }

    #pragma unroll
    for (int mt = 0; mt < 4; mt++) {
        int r0 = m0 + wm + 16 * mt + g;
        #pragma unroll
        for (int nt = 0; nt < 8; nt++) {
            int col = n0 + wn + 8 * nt + 2 * t;
            float b0 = bias[col], b1 = bias[col + 1];
            float2 v0, v1;
            if (ROUND_OUT) {
                v0 = {f2tf_f(acc[mt][nt][0] + b0), f2tf_f(acc[mt][nt][1] + b1)};
                v1 = {f2tf_f(acc[mt][nt][2] + b0), f2tf_f(acc[mt][nt][3] + b1)};
            } else {
                v0 = {acc[mt][nt][0] + b0, acc[mt][nt][1] + b1};
                v1 = {acc[mt][nt][2] + b0, acc[mt][nt][3] + b1};
            }
            *(float2*)&C[(size_t)r0 * N + col] = v0;
            *(float2*)&C[(size_t)(r0 + 8) * N + col] = v1;
        }
    }
}

__global__ __launch_bounds__(128, 2) void qkv_proj_kernel(
    const float* __restrict__ qin, const float* __restrict__ kin,
    const float* __restrict__ vin,
    const float* __restrict__ bq, const float* __restrict__ bk,
    const float* __restrict__ bv)
{
    const float* A; const float* W; const float* bias; float* C;
    if (blockIdx.z == 0)      { A = qin; W = g_wq; bias = bq; C = g_q; }
    else if (blockIdx.z == 1) { A = kin; W = g_wk; bias = bk; C = g_k; }
    else                      { A = vin; W = g_wv; bias = bv; C = g_v; }
    gemm_body<true, true>(A, W, bias, C, 512, 128);
}

__global__ __launch_bounds__(128, 2) void out_proj_kernel(
    const float* __restrict__ bo, float* __restrict__ out)
{
    gemm_body<false, false>(g_ao, g_wo, bo, out, 512, 512);
}

// ================= attention (unchanged from round 10) ======================
#define KS_STRIDE 68
#define VS_STRIDE 72
#define PB_STRIDE 68
#define K_STAGE_F (64 * KS_STRIDE)
#define V_STAGE_F (64 * VS_STRIDE)
#define ATTN_SMEM ((2 * K_STAGE_F + 2 * V_STAGE_F + 8 * 16 * PB_STRIDE) * 4) // 106496 B

__global__ __launch_bounds__(256, 2) void attn_kernel()
{
    extern __shared__ float sm[];
    float* Kst = sm;
    float* Vst = sm + 2 * K_STAGE_F;
    float* PbA = sm + 2 * K_STAGE_F + 2 * V_STAGE_F;

    int tid = threadIdx.x, lane = tid & 31, warp = tid >> 5;
    int g = lane >> 2, t = lane & 3;
    uint32_t* Pb = (uint32_t*)(PbA + warp * (16 * PB_STRIDE));

    int h  = blockIdx.x;
    int bn = blockIdx.y;
    int half = blockIdx.z;
    size_t base  = (size_t)bn * 131072 + (size_t)h * 64;
    size_t baseq = base + (size_t)half * 128 * 512;

    int f0 = tid, f1 = tid + 256, f2 = tid + 512, f3 = tid + 768;
    int r0 = f0 >> 4, c0 = (f0 & 15) * 4;
    int r1 = f1 >> 4, c1 = (f1 & 15) * 4;
    int r2 = f2 >> 4, c2 = (f2 & 15) * 4;
    int r3 = f3 >> 4, c3 = (f3 & 15) * 4;

    auto issue = [&](int chunk) {
        if (chunk < 4) {
            int kb = chunk * 64;
            float* Kd = Kst + (chunk & 1) * K_STAGE_F;
            float* Vd = Vst + (chunk & 1) * V_STAGE_F;
            cp16(smem_u32(&Kd[r0 * KS_STRIDE + c0]), &g_k[base + (size_t)(kb + r0) * 512 + c0]);
            cp16(smem_u32(&Kd[r1 * KS_STRIDE + c1]), &g_k[base + (size_t)(kb + r1) * 512 + c1]);
            cp16(smem_u32(&Kd[r2 * KS_STRIDE + c2]), &g_k[base + (size_t)(kb + r2) * 512 + c2]);
            cp16(smem_u32(&Kd[r3 * KS_STRIDE + c3]), &g_k[base + (size_t)(kb + r3) * 512 + c3]);
            cp16(smem_u32(&Vd[r0 * VS_STRIDE + c0]), &g_v[base + (size_t)(kb + r0) * 512 + c0]);
            cp16(smem_u32(&Vd[r1 * VS_STRIDE + c1]), &g_v[base + (size_t)(kb + r1) * 512 + c1]);
            cp16(smem_u32(&Vd[r2 * VS_STRIDE + c2]), &g_v[base + (size_t)(kb + r2) * 512 + c2]);
            cp16(smem_u32(&Vd[r3 * VS_STRIDE + c3]), &g_v[base + (size_t)(kb + r3) * 512 + c3]);
        }
        cp_commit();
    };

    issue(0);
    issue(1);

    // Q tile: warp's 16 rows x 64 cols; g_q pre-rounded, *0.125 is exact
    int qr0 = warp * 16;
    #pragma unroll
    for (int i = 0; i < 8; i++) {
        int f = lane + i * 32;
        int r = f >> 4, c4 = (f & 15) * 4;
        float4 qv = *(const float4*)&g_q[baseq + (size_t)(qr0 + r) * 512 + c4];
        Pb[r * PB_STRIDE + c4 + 0] = __float_as_uint(qv.x * 0.125f);
        Pb[r * PB_STRIDE + c4 + 1] = __float_as_uint(qv.y * 0.125f);
        Pb[r * PB_STRIDE + c4 + 2] = __float_as_uint(qv.z * 0.125f);
        Pb[r * PB_STRIDE + c4 + 3] = __float_as_uint(qv.w * 0.125f);
    }
    __syncwarp();

    uint32_t q[8][4];
    #pragma unroll
    for (int ks = 0; ks < 8; ks++) {
        int k0 = 8 * ks;
        q[ks][0] = Pb[g * PB_STRIDE + k0 + t];
        q[ks][1] = Pb[(g + 8) * PB_STRIDE + k0 + t];
        q[ks][2] = Pb[g * PB_STRIDE + k0 + 4 + t];
        q[ks][3] = Pb[(g + 8) * PB_STRIDE + k0 + 4 + t];
    }
    __syncwarp();

    float o[8][4] = {};
    float den0 = 0.0f, den1 = 0.0f;

    #pragma unroll 1
    for (int c = 0; c < 4; c++) {
        cp_wait<1>();
        __syncthreads();
        const float* Ks = Kst + (c & 1) * K_STAGE_F;
        const float* Vs = Vst + (c & 1) * V_STAGE_F;

        // ---- S = Q K_chunk^T ----
        float s[8][4] = {};
        #pragma unroll
        for (int ks = 0; ks < 8; ks++) {
            int k0 = 8 * ks;
            uint32_t b[8][2];
            #pragma unroll
            for (int nt = 0; nt < 8; nt++) {
                int kr = 8 * nt + g;
                b[nt][0] = __float_as_uint(Ks[kr * KS_STRIDE + k0 + t]);
                b[nt][1] = __float_as_uint(Ks[kr * KS_STRIDE + k0 + 4 + t]);
            }
            #pragma unroll
            for (int nt = 0; nt < 8; nt++)
                mma8(s[nt], q[ks], b[nt]);
        }

        // ---- exp, denom, P -> Pb ----
        #pragma unroll
        for (int nt = 0; nt < 8; nt++) {
            float e0 = __expf(s[nt][0]);
            float e1 = __expf(s[nt][1]);
            float e2 = __expf(s[nt][2]);
            float e3 = __expf(s[nt][3]);
            den0 += e0 + e1;
            den1 += e2 + e3;
            int cc = 8 * nt + 2 * t;
            uint2 p0 = {f2tf(e0), f2tf(e1)};
            uint2 p1 = {f2tf(e2), f2tf(e3)};
            *(uint2*)&Pb[g * PB_STRIDE + cc] = p0;
            *(uint2*)&Pb[(g + 8) * PB_STRIDE + cc] = p1;
        }
        __syncwarp();

        // ---- O += P V_chunk ----
        #pragma unroll
        for (int ks = 0; ks < 8; ks++) {
            int k0 = 8 * ks;
            uint32_t pa[4], b[8][2];
            pa[0] = Pb[g * PB_STRIDE + k0 + t];
            pa[1] = Pb[(g + 8) * PB_STRIDE + k0 + t];
            pa[2] = Pb[g * PB_STRIDE + k0 + 4 + t];
            pa[3] = Pb[(g + 8) * PB_STRIDE + k0 + 4 + t];
            #pragma unroll
            for (int nt = 0; nt < 8; nt++) {
                b[nt][0] = __float_as_uint(Vs[(k0 + t) * VS_STRIDE + 8 * nt + g]);
                b[nt][1] = __float_as_uint(Vs[(k0 + 4 + t) * VS_STRIDE + 8 * nt + g]);
            }
            #pragma unroll
            for (int nt = 0; nt < 8; nt++)
                mma8(o[nt], pa, b[nt]);
        }

        __syncthreads();
        issue(c + 2);
    }

    // ---- normalize, store tf32-rounded (consumed by out_proj raw) ----
    den0 += __shfl_xor_sync(0xffffffffu, den0, 1);
    den0 += __shfl_xor_sync(0xffffffffu, den0, 2);
    den1 += __shfl_xor_sync(0xffffffffu, den1, 1);
    den1 += __shfl_xor_sync(0xffffffffu, den1, 2);
    float inv0 = 1.0f / den0, inv1 = 1.0f / den1;

    int rg = qr0 + g;
    #pragma unroll
    for (int nt = 0; nt < 8; nt++) {
        int col = 8 * nt + 2 * t;
        float2 v0 = {f2tf_f(o[nt][0] * inv0), f2tf_f(o[nt][1] * inv0)};
        float2 v1 = {f2tf_f(o[nt][2] * inv1), f2tf_f(o[nt][3] * inv1)};
        *(float2*)&g_ao[baseq + (size_t)rg * 512 + col] = v0;
        *(float2*)&g_ao[baseq + (size_t)(rg + 8) * 512 + col] = v1;
    }
}

extern "C" void kernel_launch(void* const* d_in, const int* in_sizes, int n_in,
                              void* d_out, int out_size)
{
    const float* query = (const float*)d_in[0];
    const float* key   = (const float*)d_in[1];
    const float* value = (const float*)d_in[2];
    const float* Wq    = (const float*)d_in[3];
    const float* bq    = (const float*)d_in[4];
    const float* Wk    = (const float*)d_in[5];
    const float* bk    = (const float*)d_in[6];
    const float* Wv    = (const float*)d_in[7];
    const float* bv    = (const float*)d_in[8];
    const float* Wo    = (const float*)d_in[9];
    const float* bo    = (const float*)d_in[10];
    float* out = (float*)d_out;

    prep_weights_kernel<<<1024, 256>>>(Wq, Wk, Wv, Wo);

    dim3 gproj(512 / 128, 65536 / 128, 3);
    qkv_proj_kernel<<<gproj, 128>>>(query, key, value, bq, bk, bv);

    cudaFuncSetAttribute(attn_kernel,
                         cudaFuncAttributeMaxDynamicSharedMemorySize, ATTN_SMEM);
    dim3 gattn(8, 256, 2);
    attn_kernel<<<gattn, 256, ATTN_SMEM>>>();

    dim3 gout(512 / 128, 65536 / 128);
    out_proj_kernel<<<gout, 128>>>(bo, out);
}